// round 13
// baseline (speedup 1.0000x reference)
#include <cuda_runtime.h>
#include <cuda_bf16.h>
#include <cstdint>

// ---------------------------------------------------------------------------
// 2-layer bidirectional GRU. B=32, S=2048, D=256, H=256, gates=768.
//   gx = X @ W_ih^T + b_ih      (parallel GEMM)
//   step: gh = h @ W_hh^T + b_hh; r=sig(xr+hr) z=sig(xz+hz)
//         n=tanh(xn+r*hn); h' = (1-z)*n + z*h
// Scan: 8 batch-chunks x 8 ranks = 64 CTAs (8-CTA clusters, one per chunk).
// Each 256-thread CTA runs BOTH directions of its chunk: warps 0-3 = fwd,
// warps 4-7 = bwd, sharing the 98KB W_hh slice in smem -> 2 warps/SMSP so
// stalls of one direction are hidden by issue of the other. h exchanged via
// st.shared::cluster into per-(parity,dir) buffers; one barrier.cluster/step.
// ---------------------------------------------------------------------------

#define S_LEN  2048
#define NBATCH 32
#define HID    256
#define G3     768
#define OUTW   512
#define BC     4          // batches per chunk
#define CSIZE  8          // CTAs per cluster (= j-ranks)
#define JPC    32         // j's per CTA
#define HPAD   260        // padded row stride (floats)
#define SCTH   256

// smem layout (floats): W [3][JPC][HPAD] then h [2 par][2 dir][BC][HPAD]
#define SW_FLOATS (3 * JPC * HPAD)              // 24960
#define SH_FLOATS (2 * 2 * BC * HPAD)           // 4160
#define SMEM_BYTES ((SW_FLOATS + SH_FLOATS) * 4)   // 116480

__device__ float g_gx[(size_t)NBATCH * S_LEN * G3];     // [b*S+s][768]
__device__ float g_out0[(size_t)NBATCH * S_LEN * OUTW]; // layer0 output

// ---- f32x2 helpers --------------------------------------------------------
__device__ __forceinline__ void fma2(uint64_t& d, uint64_t a, uint64_t b) {
    asm("fma.rn.f32x2 %0, %1, %2, %0;" : "+l"(d) : "l"(a), "l"(b));
}
__device__ __forceinline__ uint64_t pk(float lo, float hi) {
    uint64_t r; asm("mov.b64 %0, {%1, %2};" : "=l"(r) : "f"(lo), "f"(hi)); return r;
}
__device__ __forceinline__ float upks(uint64_t v) {
    float lo, hi; asm("mov.b64 {%0, %1}, %2;" : "=f"(lo), "=f"(hi) : "l"(v));
    return lo + hi;
}
__device__ __forceinline__ float fsig(float x) {
    return __fdividef(1.f, 1.f + __expf(-x));
}
__device__ __forceinline__ float ftanh(float x) {
    return 1.f - __fdividef(2.f, __expf(2.f * x) + 1.f);
}

// ---------------------------------------------------------------------------
// GEMM: C[m][n] = sum_k A[m][k]*W[n][k] + bias[n].  A:[65536][K], W:[768][K].
// Block 128(m) x 64(n), BK=8, 256 threads, 8x4 f32x2 accumulators.
// ---------------------------------------------------------------------------
__global__ void __launch_bounds__(256) k_gemm(
    const float* __restrict__ Aext, const float* __restrict__ W,
    const float* __restrict__ bias, int K, int useInternalA)
{
    __shared__ float As[8][132];
    __shared__ float Bs[8][68];

    const float* A = useInternalA ? &g_out0[0] : Aext;
    float* C = &g_gx[0];

    const int tid = threadIdx.x;
    const int bm = blockIdx.x, bn = blockIdx.y;
    const int tx = tid & 15, ty = tid >> 4;

    const int lr = tid >> 1, lq = (tid & 1) * 4;
    const float* Ap = A + (size_t)(bm * 128 + lr) * K + lq;
    const float* Bp = W + (size_t)(bn * 64 + (lr & 63)) * K + lq;
    const bool loadB = (tid < 128);

    uint64_t acc[8][4];
#pragma unroll
    for (int i = 0; i < 8; ++i)
#pragma unroll
        for (int j = 0; j < 4; ++j) acc[i][j] = 0ull;

    float4 av = *(const float4*)Ap;
    float4 bv = loadB ? *(const float4*)Bp : make_float4(0.f, 0.f, 0.f, 0.f);

    for (int kt = 0; kt < K; kt += 8) {
        __syncthreads();
        As[lq + 0][lr] = av.x; As[lq + 1][lr] = av.y;
        As[lq + 2][lr] = av.z; As[lq + 3][lr] = av.w;
        if (loadB) {
            Bs[lq + 0][lr] = bv.x; Bs[lq + 1][lr] = bv.y;
            Bs[lq + 2][lr] = bv.z; Bs[lq + 3][lr] = bv.w;
        }
        __syncthreads();
        if (kt + 8 < K) {
            av = *(const float4*)(Ap + kt + 8);
            if (loadB) bv = *(const float4*)(Bp + kt + 8);
        }
#pragma unroll
        for (int k2 = 0; k2 < 4; ++k2) {
            float4 aL0 = *(const float4*)&As[2 * k2][ty * 8];
            float4 aH0 = *(const float4*)&As[2 * k2][ty * 8 + 4];
            float4 aL1 = *(const float4*)&As[2 * k2 + 1][ty * 8];
            float4 aH1 = *(const float4*)&As[2 * k2 + 1][ty * 8 + 4];
            float4 b0  = *(const float4*)&Bs[2 * k2][tx * 4];
            float4 b1  = *(const float4*)&Bs[2 * k2 + 1][tx * 4];
            uint64_t am[8], bb[4];
            am[0] = pk(aL0.x, aL1.x); am[1] = pk(aL0.y, aL1.y);
            am[2] = pk(aL0.z, aL1.z); am[3] = pk(aL0.w, aL1.w);
            am[4] = pk(aH0.x, aH1.x); am[5] = pk(aH0.y, aH1.y);
            am[6] = pk(aH0.z, aH1.z); am[7] = pk(aH0.w, aH1.w);
            bb[0] = pk(b0.x, b1.x);   bb[1] = pk(b0.y, b1.y);
            bb[2] = pk(b0.z, b1.z);   bb[3] = pk(b0.w, b1.w);
#pragma unroll
            for (int i = 0; i < 8; ++i)
#pragma unroll
                for (int j = 0; j < 4; ++j) fma2(acc[i][j], am[i], bb[j]);
        }
    }

    const int n0 = bn * 64 + tx * 4;
    float4 b4 = *(const float4*)&bias[n0];
#pragma unroll
    for (int i = 0; i < 8; ++i) {
        size_t m = (size_t)bm * 128 + ty * 8 + i;
        float4 o;
        o.x = upks(acc[i][0]) + b4.x;
        o.y = upks(acc[i][1]) + b4.y;
        o.z = upks(acc[i][2]) + b4.z;
        o.w = upks(acc[i][3]) + b4.w;
        *(float4*)&C[m * G3 + n0] = o;
    }
}

// ---------------------------------------------------------------------------
// Cluster scan, dual-direction CTAs. Grid = 64 CTAs x 256 thr, cluster (8).
//   chunk = bid>>3 (b0 = chunk*4), rank = bid&7.
//   dir = tid>>7 (warps 0-3 fwd, 4-7 bwd); li = tid&127:
//   w = li>>5, lane: b = (lane>>3)&3, jl = w*8 + (lane&7), jg = rank*32+jl.
// ---------------------------------------------------------------------------
__global__ void __launch_bounds__(SCTH, 1) __cluster_dims__(CSIZE, 1, 1)
k_scan(const float* __restrict__ Whh, const float* __restrict__ bhh,
       float* __restrict__ dout, int layer, int write_hn)
{
    extern __shared__ float smem[];
    float* sW = smem;                  // [3][JPC][HPAD]
    float* sh = smem + SW_FLOATS;      // [2 par][2 dir][BC][HPAD]

    const int tid = threadIdx.x;
    const int rank = blockIdx.x & (CSIZE - 1);
    const int chunk = blockIdx.x >> 3;
    const int b0 = chunk * BC;

    const int dir = tid >> 7;            // 0 fwd, 1 bwd
    const int li = tid & 127;
    const int w = li >> 5, lane = li & 31;
    const int b = lane >> 3;             // 0..3
    const int jl = w * 8 + (lane & 7);   // 0..31
    const int jg = rank * JPC + jl;      // 0..255

    const float* gx = &g_gx[0];
    float* out = layer ? dout : &g_out0[0];
    float* hn = write_hn ? dout + (size_t)NBATCH * S_LEN * OUTW : nullptr;

    // load W slice: 96 rows x 256 floats (shared by both directions)
    for (int i = tid; i < 96 * 64; i += SCTH) {
        int r = i >> 6, k4 = i & 63;
        int gi = r >> 5, jr = r & 31;
        *(float4*)&sW[(gi * JPC + jr) * HPAD + k4 * 4] =
            *(const float4*)&Whh[(size_t)(gi * HID + rank * JPC + jr) * HID + k4 * 4];
    }
    for (int i = tid; i < SH_FLOATS; i += SCTH) sh[i] = 0.f;

    const float bhr = __ldg(&bhh[jg]);
    const float bhz = __ldg(&bhh[HID + jg]);
    const float bhn = __ldg(&bhh[2 * HID + jg]);

    uint32_t sh_u32;
    {
        uint64_t tmp;
        asm("cvta.to.shared.u64 %0, %1;" : "=l"(tmp) : "l"(sh));
        sh_u32 = (uint32_t)tmp;
    }
    uint32_t peer[CSIZE];
#pragma unroll
    for (int r = 0; r < CSIZE; ++r)
        asm("mapa.shared::cluster.u32 %0, %1, %2;"
            : "=r"(peer[r]) : "r"(sh_u32), "r"(r));

    const float* gxbase = gx + (size_t)(b0 + b) * S_LEN * G3 + jg;
    float* outbase = out + ((size_t)(b0 + b) * S_LEN) * OUTW + dir * HID + jg;

    __syncthreads();
    asm volatile("barrier.cluster.arrive.aligned;" ::: "memory");
    asm volatile("barrier.cluster.wait.aligned;" ::: "memory");

    // gx prefetch for t = 0
    int tt0 = dir ? (S_LEN - 1) : 0;
    float gxr = __ldg(gxbase + (size_t)tt0 * G3);
    float gxz = __ldg(gxbase + (size_t)tt0 * G3 + HID);
    float gxn = __ldg(gxbase + (size_t)tt0 * G3 + 2 * HID);

    float hprev = 0.f;   // own element; carried in-register across steps

    for (int t = 0; t < S_LEN; ++t) {
        const int tt = dir ? (S_LEN - 1 - t) : t;
        const int par = t & 1;

        // three fused dots over k=256, fully unrolled
        uint64_t ar0 = 0ull, ar1 = 0ull, az0 = 0ull, az1 = 0ull,
                 an0 = 0ull, an1 = 0ull;
        {
            const ulonglong2* __restrict__ hp =
                (const ulonglong2*)&sh[((par * 2 + dir) * BC + b) * HPAD];
            const ulonglong2* __restrict__ wr =
                (const ulonglong2*)&sW[(0 * JPC + jl) * HPAD];
            const ulonglong2* __restrict__ wz =
                (const ulonglong2*)&sW[(1 * JPC + jl) * HPAD];
            const ulonglong2* __restrict__ wn =
                (const ulonglong2*)&sW[(2 * JPC + jl) * HPAD];
#pragma unroll
            for (int k4 = 0; k4 < 64; ++k4) {
                ulonglong2 hv = hp[k4];
                ulonglong2 rv = wr[k4];
                ulonglong2 zv = wz[k4];
                ulonglong2 nv = wn[k4];
                fma2(ar0, hv.x, rv.x); fma2(ar1, hv.y, rv.y);
                fma2(az0, hv.x, zv.x); fma2(az1, hv.y, zv.y);
                fma2(an0, hv.x, nv.x); fma2(an1, hv.y, nv.y);
            }
        }
        float hr = upks(ar0) + upks(ar1) + bhr;
        float hz = upks(az0) + upks(az1) + bhz;
        float hv = upks(an0) + upks(an1) + bhn;

        float rg = fsig(gxr + hr);
        float zg = fsig(gxz + hz);
        float ng = ftanh(gxn + rg * hv);
        float hnew = (1.f - zg) * ng + zg * hprev;
        hprev = hnew;

        // scatter hnew into every cluster CTA's sh[par^1][dir][b][jg]
        const uint32_t off =
            (uint32_t)(((((par ^ 1) * 2 + dir) * BC + b) * HPAD + jg) * 4);
#pragma unroll
        for (int r = 0; r < CSIZE; ++r)
            asm volatile("st.shared::cluster.f32 [%0], %1;"
                         :: "r"(peer[r] + off), "f"(hnew) : "memory");

        // release our DSMEM stores; overlap global traffic with barrier wait
        asm volatile("barrier.cluster.arrive.aligned;" ::: "memory");

        outbase[(size_t)tt * OUTW] = hnew;
        if (t + 1 < S_LEN) {
            const int tn = dir ? (S_LEN - 2 - t) : (t + 1);
            const float* gp = gxbase + (size_t)tn * G3;
            gxr = __ldg(gp);
            gxz = __ldg(gp + HID);
            gxn = __ldg(gp + 2 * HID);
        } else if (hn) {
            hn[((size_t)(layer * 2 + dir) * NBATCH + b0 + b) * HID + jg] = hnew;
        }

        asm volatile("barrier.cluster.wait.aligned;" ::: "memory");
    }
}

// ---------------------------------------------------------------------------
extern "C" void kernel_launch(void* const* d_in, const int* in_sizes, int n_in,
                              void* d_out, int out_size)
{
    const float* X     = (const float*)d_in[0];
    const float* Wih0  = (const float*)d_in[1];
    const float* Whh0  = (const float*)d_in[2];
    const float* bih0  = (const float*)d_in[3];
    const float* bhh0  = (const float*)d_in[4];
    const float* Wih1  = (const float*)d_in[5];
    const float* Whh1  = (const float*)d_in[6];
    const float* bih1  = (const float*)d_in[7];
    const float* bhh1  = (const float*)d_in[8];
    float* out = (float*)d_out;

    const long long need_hn =
        (long long)NBATCH * S_LEN * OUTW + 4LL * NBATCH * HID;
    int write_hn = ((long long)out_size >= need_hn) ? 1 : 0;

    cudaFuncSetAttribute(k_scan, cudaFuncAttributeMaxDynamicSharedMemorySize,
                         SMEM_BYTES);

    dim3 ggrid(512, 12);

    k_gemm<<<ggrid, 256>>>(X, Wih0, bih0, 256, 0);
    k_scan<<<64, SCTH, SMEM_BYTES>>>(Whh0, bhh0, out, 0, write_hn);

    k_gemm<<<ggrid, 256>>>(nullptr, Wih1, bih1, 512, 1);
    k_scan<<<64, SCTH, SMEM_BYTES>>>(Whh1, bhh1, out, 1, write_hn);
}

// round 14
// speedup vs baseline: 1.2911x; 1.2911x over previous
#include <cuda_runtime.h>
#include <cuda_bf16.h>
#include <cstdint>

// ---------------------------------------------------------------------------
// 2-layer bidirectional GRU. B=32, S=2048, D=256, H=256, gates=768.
//   gx = X @ W_ih^T + b_ih      (parallel GEMM)
//   step: gh = h @ W_hh^T + b_hh; r=sig(xr+hr) z=sig(xz+hz)
//         n=tanh(xn+r*hn); h' = (1-z)*n + z*h
// Scan: 16 groups (2 dirs x 8 batch-chunks of 4), each an 8-CTA cluster.
// R14 dot layout (smem-BW bound fix): warp g in {r,z,n}, lane = j. Each lane
// computes its gate row's dot for ALL 4 batches sharing one W load per k4
// (W traffic /4 vs R12) with W transposed in smem ([g][k4][j][4]) for
// conflict-free lane-consecutive LDS.128; h loads are warp-uniform (1 wf).
// Partials exchanged via a 1.5KB smem buffer; gate math on (b,j) threads;
// h' scattered cluster-wide via st.shared::cluster; one barrier.cluster/step.
// ---------------------------------------------------------------------------

#define S_LEN  2048
#define NBATCH 32
#define HID    256
#define G3     768
#define OUTW   512
#define BC     4          // batches per group
#define CSIZE  8          // CTAs per cluster (= j-ranks)
#define JPC    32         // j's per CTA
#define HPAD   260        // h row stride (floats), 16B aligned
#define SCTH   128

// smem (floats): Wt [3][64][32][4] | h [2 par][BC][HPAD] | sgh [3][32][4]
#define SWT_FLOATS (3 * 64 * JPC * 4)        // 24576
#define SH_FLOATS  (2 * BC * HPAD)           // 2080
#define SGH_FLOATS (3 * JPC * 4)             // 384
#define SMEM_BYTES ((SWT_FLOATS + SH_FLOATS + SGH_FLOATS) * 4)

__device__ float g_gx[(size_t)NBATCH * S_LEN * G3];     // [b*S+s][768]
__device__ float g_out0[(size_t)NBATCH * S_LEN * OUTW]; // layer0 output

// ---- f32x2 helpers --------------------------------------------------------
__device__ __forceinline__ void fma2(uint64_t& d, uint64_t a, uint64_t b) {
    asm("fma.rn.f32x2 %0, %1, %2, %0;" : "+l"(d) : "l"(a), "l"(b));
}
__device__ __forceinline__ uint64_t pk(float lo, float hi) {
    uint64_t r; asm("mov.b64 %0, {%1, %2};" : "=l"(r) : "f"(lo), "f"(hi)); return r;
}
__device__ __forceinline__ float upks(uint64_t v) {
    float lo, hi; asm("mov.b64 {%0, %1}, %2;" : "=f"(lo), "=f"(hi) : "l"(v));
    return lo + hi;
}
__device__ __forceinline__ float fsig(float x) {
    return __fdividef(1.f, 1.f + __expf(-x));
}
__device__ __forceinline__ float ftanh(float x) {
    return 1.f - __fdividef(2.f, __expf(2.f * x) + 1.f);
}

// ---------------------------------------------------------------------------
// GEMM: C[m][n] = sum_k A[m][k]*W[n][k] + bias[n].  A:[65536][K], W:[768][K].
// ---------------------------------------------------------------------------
__global__ void __launch_bounds__(256) k_gemm(
    const float* __restrict__ Aext, const float* __restrict__ W,
    const float* __restrict__ bias, int K, int useInternalA)
{
    __shared__ float As[8][132];
    __shared__ float Bs[8][68];

    const float* A = useInternalA ? &g_out0[0] : Aext;
    float* C = &g_gx[0];

    const int tid = threadIdx.x;
    const int bm = blockIdx.x, bn = blockIdx.y;
    const int tx = tid & 15, ty = tid >> 4;

    const int lr = tid >> 1, lq = (tid & 1) * 4;
    const float* Ap = A + (size_t)(bm * 128 + lr) * K + lq;
    const float* Bp = W + (size_t)(bn * 64 + (lr & 63)) * K + lq;
    const bool loadB = (tid < 128);

    uint64_t acc[8][4];
#pragma unroll
    for (int i = 0; i < 8; ++i)
#pragma unroll
        for (int j = 0; j < 4; ++j) acc[i][j] = 0ull;

    float4 av = *(const float4*)Ap;
    float4 bv = loadB ? *(const float4*)Bp : make_float4(0.f, 0.f, 0.f, 0.f);

    for (int kt = 0; kt < K; kt += 8) {
        __syncthreads();
        As[lq + 0][lr] = av.x; As[lq + 1][lr] = av.y;
        As[lq + 2][lr] = av.z; As[lq + 3][lr] = av.w;
        if (loadB) {
            Bs[lq + 0][lr] = bv.x; Bs[lq + 1][lr] = bv.y;
            Bs[lq + 2][lr] = bv.z; Bs[lq + 3][lr] = bv.w;
        }
        __syncthreads();
        if (kt + 8 < K) {
            av = *(const float4*)(Ap + kt + 8);
            if (loadB) bv = *(const float4*)(Bp + kt + 8);
        }
#pragma unroll
        for (int k2 = 0; k2 < 4; ++k2) {
            float4 aL0 = *(const float4*)&As[2 * k2][ty * 8];
            float4 aH0 = *(const float4*)&As[2 * k2][ty * 8 + 4];
            float4 aL1 = *(const float4*)&As[2 * k2 + 1][ty * 8];
            float4 aH1 = *(const float4*)&As[2 * k2 + 1][ty * 8 + 4];
            float4 b0  = *(const float4*)&Bs[2 * k2][tx * 4];
            float4 b1  = *(const float4*)&Bs[2 * k2 + 1][tx * 4];
            uint64_t am[8], bb[4];
            am[0] = pk(aL0.x, aL1.x); am[1] = pk(aL0.y, aL1.y);
            am[2] = pk(aL0.z, aL1.z); am[3] = pk(aL0.w, aL1.w);
            am[4] = pk(aH0.x, aH1.x); am[5] = pk(aH0.y, aH1.y);
            am[6] = pk(aH0.z, aH1.z); am[7] = pk(aH0.w, aH1.w);
            bb[0] = pk(b0.x, b1.x);   bb[1] = pk(b0.y, b1.y);
            bb[2] = pk(b0.z, b1.z);   bb[3] = pk(b0.w, b1.w);
#pragma unroll
            for (int i = 0; i < 8; ++i)
#pragma unroll
                for (int j = 0; j < 4; ++j) fma2(acc[i][j], am[i], bb[j]);
        }
    }

    const int n0 = bn * 64 + tx * 4;
    float4 b4 = *(const float4*)&bias[n0];
#pragma unroll
    for (int i = 0; i < 8; ++i) {
        size_t m = (size_t)bm * 128 + ty * 8 + i;
        float4 o;
        o.x = upks(acc[i][0]) + b4.x;
        o.y = upks(acc[i][1]) + b4.y;
        o.z = upks(acc[i][2]) + b4.z;
        o.w = upks(acc[i][3]) + b4.w;
        *(float4*)&C[m * G3 + n0] = o;
    }
}

// ---------------------------------------------------------------------------
// Cluster scan. Grid = 128 CTAs x 128 threads, cluster (8,1,1).
//   group gcl = bid>>3 (dir = gcl&1, b0 = (gcl>>1)*4), rank = bid&7.
// Dot phase (tid<96): warp = gate, lane = j; 4 batch dots per thread.
// Gate phase (all 128): b = lane>>3, jl = w*8+(lane&7), jg = rank*32+jl.
// ---------------------------------------------------------------------------
__global__ void __launch_bounds__(SCTH, 1) __cluster_dims__(CSIZE, 1, 1)
k_scan(const float* __restrict__ Whh, const float* __restrict__ bhh,
       float* __restrict__ dout, int layer, int write_hn)
{
    extern __shared__ float smem[];
    float* sWt = smem;                              // [3][64][32][4]
    float* sh  = smem + SWT_FLOATS;                 // [2][BC][HPAD]
    float* sgh = smem + SWT_FLOATS + SH_FLOATS;     // [3][32][4]

    const int tid = threadIdx.x;
    const int rank = blockIdx.x & (CSIZE - 1);
    const int gcl = blockIdx.x >> 3;
    const int dir = gcl & 1;
    const int b0 = (gcl >> 1) * BC;

    const int w = tid >> 5, lane = tid & 31;
    // gate-phase mapping
    const int b = lane >> 3;             // 0..3
    const int jl = w * 8 + (lane & 7);   // 0..31
    const int jg = rank * JPC + jl;      // 0..255

    const float* gx = &g_gx[0];
    float* out = layer ? dout : &g_out0[0];
    float* hn = write_hn ? dout + (size_t)NBATCH * S_LEN * OUTW : nullptr;

    // load W transposed: sWt[g][k4][j][0..3] = Whh[g*HID + rank*32 + j][k4*4..]
    for (int i = tid; i < 3 * 64 * JPC; i += SCTH) {
        int g = i >> 11;             // /2048
        int rem = i & 2047;
        int k4 = rem >> 5;
        int j = rem & 31;
        float4 v = *(const float4*)
            &Whh[(size_t)(g * HID + rank * JPC + j) * HID + k4 * 4];
        *(float4*)&sWt[((g * 64 + k4) * JPC + j) * 4] = v;
    }
    for (int i = tid; i < SH_FLOATS; i += SCTH) sh[i] = 0.f;

    const float bhr = __ldg(&bhh[jg]);
    const float bhz = __ldg(&bhh[HID + jg]);
    const float bhn = __ldg(&bhh[2 * HID + jg]);

    uint32_t sh_u32;
    {
        uint64_t tmp;
        asm("cvta.to.shared.u64 %0, %1;" : "=l"(tmp) : "l"(sh));
        sh_u32 = (uint32_t)tmp;
    }
    uint32_t peer[CSIZE];
#pragma unroll
    for (int r = 0; r < CSIZE; ++r)
        asm("mapa.shared::cluster.u32 %0, %1, %2;"
            : "=r"(peer[r]) : "r"(sh_u32), "r"(r));

    const float* gxbase = gx + (size_t)(b0 + b) * S_LEN * G3 + jg;
    float* outbase = out + ((size_t)(b0 + b) * S_LEN) * OUTW + dir * HID + jg;

    __syncthreads();
    asm volatile("barrier.cluster.arrive.aligned;" ::: "memory");
    asm volatile("barrier.cluster.wait.aligned;" ::: "memory");

    // gx prefetch for t = 0
    int tt0 = dir ? (S_LEN - 1) : 0;
    float gxr = __ldg(gxbase + (size_t)tt0 * G3);
    float gxz = __ldg(gxbase + (size_t)tt0 * G3 + HID);
    float gxn = __ldg(gxbase + (size_t)tt0 * G3 + 2 * HID);

    float hprev = 0.f;

    // dot-phase W pointer: gate = w (warps 0-2), lane = j
    const ulonglong2* wbase =
        (const ulonglong2*)(sWt + (w < 3 ? w : 0) * (64 * JPC * 4)) + lane;

    for (int t = 0; t < S_LEN; ++t) {
        const int tt = dir ? (S_LEN - 1 - t) : t;
        const int par = t & 1;

        if (tid < 96) {
            // 4 batch dots for gate w, j = lane, k = 0..255
            const ulonglong2* __restrict__ hp0 =
                (const ulonglong2*)&sh[(par * BC + 0) * HPAD];
            const ulonglong2* __restrict__ hp1 =
                (const ulonglong2*)&sh[(par * BC + 1) * HPAD];
            const ulonglong2* __restrict__ hp2 =
                (const ulonglong2*)&sh[(par * BC + 2) * HPAD];
            const ulonglong2* __restrict__ hp3 =
                (const ulonglong2*)&sh[(par * BC + 3) * HPAD];
            uint64_t a00 = 0ull, a01 = 0ull, a10 = 0ull, a11 = 0ull,
                     a20 = 0ull, a21 = 0ull, a30 = 0ull, a31 = 0ull;
#pragma unroll
            for (int k4 = 0; k4 < 64; ++k4) {
                ulonglong2 wv = wbase[k4 * JPC];   // lane-consecutive 16B
                ulonglong2 h0 = hp0[k4];
                ulonglong2 h1 = hp1[k4];
                ulonglong2 h2 = hp2[k4];
                ulonglong2 h3 = hp3[k4];
                fma2(a00, h0.x, wv.x); fma2(a01, h0.y, wv.y);
                fma2(a10, h1.x, wv.x); fma2(a11, h1.y, wv.y);
                fma2(a20, h2.x, wv.x); fma2(a21, h2.y, wv.y);
                fma2(a30, h3.x, wv.x); fma2(a31, h3.y, wv.y);
            }
            float4 p;
            p.x = upks(a00) + upks(a01);
            p.y = upks(a10) + upks(a11);
            p.z = upks(a20) + upks(a21);
            p.w = upks(a30) + upks(a31);
            *(float4*)&sgh[(w * JPC + lane) * 4] = p;   // [g][j][b]
        }
        __syncthreads();

        // gate phase: all 128 threads, element (b, jl)
        float hr = sgh[(0 * JPC + jl) * 4 + b] + bhr;
        float hz = sgh[(1 * JPC + jl) * 4 + b] + bhz;
        float hv = sgh[(2 * JPC + jl) * 4 + b] + bhn;

        float rg = fsig(gxr + hr);
        float zg = fsig(gxz + hz);
        float ng = ftanh(gxn + rg * hv);
        float hnew = (1.f - zg) * ng + zg * hprev;
        hprev = hnew;

        // scatter hnew into every cluster CTA's sh[par^1][b][jg]
        const uint32_t off = (uint32_t)((((par ^ 1) * BC + b) * HPAD + jg) * 4);
#pragma unroll
        for (int r = 0; r < CSIZE; ++r)
            asm volatile("st.shared::cluster.f32 [%0], %1;"
                         :: "r"(peer[r] + off), "f"(hnew) : "memory");

        asm volatile("barrier.cluster.arrive.aligned;" ::: "memory");

        outbase[(size_t)tt * OUTW] = hnew;
        if (t + 1 < S_LEN) {
            const int tn = dir ? (S_LEN - 2 - t) : (t + 1);
            const float* gp = gxbase + (size_t)tn * G3;
            gxr = __ldg(gp);
            gxz = __ldg(gp + HID);
            gxn = __ldg(gp + 2 * HID);
        } else if (hn) {
            hn[((size_t)(layer * 2 + dir) * NBATCH + b0 + b) * HID + jg] = hnew;
        }

        asm volatile("barrier.cluster.wait.aligned;" ::: "memory");
    }
}

// ---------------------------------------------------------------------------
extern "C" void kernel_launch(void* const* d_in, const int* in_sizes, int n_in,
                              void* d_out, int out_size)
{
    const float* X     = (const float*)d_in[0];
    const float* Wih0  = (const float*)d_in[1];
    const float* Whh0  = (const float*)d_in[2];
    const float* bih0  = (const float*)d_in[3];
    const float* bhh0  = (const float*)d_in[4];
    const float* Wih1  = (const float*)d_in[5];
    const float* Whh1  = (const float*)d_in[6];
    const float* bih1  = (const float*)d_in[7];
    const float* bhh1  = (const float*)d_in[8];
    float* out = (float*)d_out;

    const long long need_hn =
        (long long)NBATCH * S_LEN * OUTW + 4LL * NBATCH * HID;
    int write_hn = ((long long)out_size >= need_hn) ? 1 : 0;

    cudaFuncSetAttribute(k_scan, cudaFuncAttributeMaxDynamicSharedMemorySize,
                         SMEM_BYTES);

    dim3 ggrid(512, 12);

    k_gemm<<<ggrid, 256>>>(X, Wih0, bih0, 256, 0);
    k_scan<<<128, SCTH, SMEM_BYTES>>>(Whh0, bhh0, out, 0, write_hn);

    k_gemm<<<ggrid, 256>>>(nullptr, Wih1, bih1, 512, 1);
    k_scan<<<128, SCTH, SMEM_BYTES>>>(Whh1, bhh1, out, 1, write_hn);
}